// round 1
// baseline (speedup 1.0000x reference)
#include <cuda_runtime.h>
#include <math.h>

#define T 256
#define H 1024
#define E 256
#define I_DIM 256

// ---- scratch (static device allocations only; no cudaMalloc) ----
__device__ int   d_cnt[E];
__device__ int   d_tokbuf[E * T];
__device__ float d_wbuf[E * T];
__device__ float d_S[T * I_DIM];   // shared-expert intermediate activations

// ============================================================
// 0) zero per-expert counters
// ============================================================
__global__ void k_zero() { d_cnt[threadIdx.x] = 0; }

// ============================================================
// 1) gate logits + noaux_tc routing. 4 tokens per block, 256 thr.
// ============================================================
__global__ void k_route(const float* __restrict__ x,
                        const float* __restrict__ gw,
                        const float* __restrict__ ebias)
{
    __shared__ float xs[4][H];        // 16 KB
    __shared__ float s_scores[4][E];  // raw sigmoid scores
    __shared__ float s_sc[4][E];      // scores + bias

    int tid  = threadIdx.x;
    int lane = tid & 31;
    int wid  = tid >> 5;
    int t0   = blockIdx.x * 4;

    for (int t = 0; t < 4; t++)
        for (int k = tid; k < H; k += 256)
            xs[t][k] = x[(t0 + t) * H + k];
    __syncthreads();

    // logits: warp `wid` handles experts [wid*32, wid*32+32)
    for (int eo = 0; eo < 32; eo++) {
        int e = wid * 32 + eo;
        const float* wr = gw + e * H;
        float a0 = 0.f, a1 = 0.f, a2 = 0.f, a3 = 0.f;
        #pragma unroll 4
        for (int k = 0; k < 32; k++) {
            float wv = wr[k * 32 + lane];
            a0 += wv * xs[0][k * 32 + lane];
            a1 += wv * xs[1][k * 32 + lane];
            a2 += wv * xs[2][k * 32 + lane];
            a3 += wv * xs[3][k * 32 + lane];
        }
        for (int off = 16; off; off >>= 1) {
            a0 += __shfl_xor_sync(~0u, a0, off);
            a1 += __shfl_xor_sync(~0u, a1, off);
            a2 += __shfl_xor_sync(~0u, a2, off);
            a3 += __shfl_xor_sync(~0u, a3, off);
        }
        if (lane == 0) {
            float b = ebias[e];
            float s;
            s = 1.f / (1.f + expf(-a0)); s_scores[0][e] = s; s_sc[0][e] = s + b;
            s = 1.f / (1.f + expf(-a1)); s_scores[1][e] = s; s_sc[1][e] = s + b;
            s = 1.f / (1.f + expf(-a2)); s_scores[2][e] = s; s_sc[2][e] = s + b;
            s = 1.f / (1.f + expf(-a3)); s_scores[3][e] = s; s_sc[3][e] = s + b;
        }
    }
    __syncthreads();

    // routing: warps 0..3 each handle one token
    if (wid < 4) {
        int t     = wid;
        int tglob = t0 + t;

        // per-group top-2 sum (8 groups of 32)
        float gs[8];
        #pragma unroll
        for (int g = 0; g < 8; g++) {
            float v  = s_sc[t][g * 32 + lane];
            float m1 = v; int i1 = lane;
            for (int off = 16; off; off >>= 1) {
                float ov = __shfl_xor_sync(~0u, m1, off);
                int   oi = __shfl_xor_sync(~0u, i1, off);
                if (ov > m1 || (ov == m1 && oi < i1)) { m1 = ov; i1 = oi; }
            }
            float v2 = (lane == i1) ? -INFINITY : v;
            for (int off = 16; off; off >>= 1)
                v2 = fmaxf(v2, __shfl_xor_sync(~0u, v2, off));
            gs[g] = m1 + v2;
        }

        // top-4 groups (identical serial pass in every lane)
        unsigned gmask = 0;
        #pragma unroll
        for (int r = 0; r < 4; r++) {
            float bv = -INFINITY; int bg = 0;
            #pragma unroll
            for (int g = 0; g < 8; g++)
                if (!((gmask >> g) & 1) && gs[g] > bv) { bv = gs[g]; bg = g; }
            gmask |= 1u << bg;
        }

        // top-8 experts among allowed groups; lane owns e = lane + 32*j (group j)
        float mv[8];
        #pragma unroll
        for (int j = 0; j < 8; j++)
            mv[j] = ((gmask >> j) & 1) ? s_sc[t][lane + 32 * j] : -INFINITY;

        int sel[8];
        #pragma unroll
        for (int r = 0; r < 8; r++) {
            float bv = -INFINITY; int be = 1 << 30;
            #pragma unroll
            for (int j = 0; j < 8; j++) {
                int e = lane + 32 * j;
                if (mv[j] > bv || (mv[j] == bv && e < be)) { bv = mv[j]; be = e; }
            }
            for (int off = 16; off; off >>= 1) {
                float ov = __shfl_xor_sync(~0u, bv, off);
                int   oe = __shfl_xor_sync(~0u, be, off);
                if (ov > bv || (ov == bv && oe < be)) { bv = ov; be = oe; }
            }
            sel[r] = be;
            if ((be & 31) == lane) mv[be >> 5] = -INFINITY;
        }

        // weights from RAW sigmoid scores, normalized, * 2.5
        float myv = (lane < 8) ? s_scores[t][sel[lane]] : 0.f;
        float sum = myv;
        for (int off = 16; off; off >>= 1)
            sum += __shfl_xor_sync(~0u, sum, off);
        if (lane < 8) {
            float wt = myv / (sum + 1e-20f) * 2.5f;
            int e = sel[lane];
            int pos = atomicAdd(&d_cnt[e], 1);
            d_tokbuf[e * T + pos] = tglob;
            d_wbuf[e * T + pos]  = wt;
        }
    }
}

// ============================================================
// 2a) shared expert up/gate: S[t,i] = silu(x@swg)[t,i] * (x@swu)[t,i]
//     grid 64 (4 tokens/block), 256 threads = i columns
// ============================================================
__global__ void k_shared_a(const float* __restrict__ x,
                           const float* __restrict__ swg,
                           const float* __restrict__ swu)
{
    int tid = threadIdx.x;
    int t0  = blockIdx.x * 4;
    const float* x0 = x + (size_t)t0 * H;
    float a1[4] = {0, 0, 0, 0}, a3[4] = {0, 0, 0, 0};
    for (int h = 0; h < H; h++) {
        float g = swg[h * I_DIM + tid];
        float u = swu[h * I_DIM + tid];
        #pragma unroll
        for (int j = 0; j < 4; j++) {
            float xv = __ldg(x0 + j * H + h);
            a1[j] += xv * g;
            a3[j] += xv * u;
        }
    }
    #pragma unroll
    for (int j = 0; j < 4; j++) {
        float v = a1[j];
        d_S[(t0 + j) * I_DIM + tid] = (v / (1.f + expf(-v))) * a3[j];
    }
}

// ============================================================
// 2b) shared expert down-proj, writes y (initializes the output).
//     grid 64 = 16 token-chunks x 4 h-chunks, 256 threads
// ============================================================
__global__ void k_shared_b(const float* __restrict__ swd, float* __restrict__ y)
{
    __shared__ float ps[16][I_DIM];  // 16 KB
    int tid = threadIdx.x;
    int tc  = blockIdx.x >> 2;
    int hb  = blockIdx.x & 3;
    int t0  = tc * 16;
    #pragma unroll
    for (int j = 0; j < 16; j++)
        ps[j][tid] = d_S[(t0 + j) * I_DIM + tid];
    __syncthreads();

    int h = hb * 256 + tid;
    float ad[16];
    #pragma unroll
    for (int j = 0; j < 16; j++) ad[j] = 0.f;
    for (int i = 0; i < I_DIM; i++) {
        float wv = swd[i * H + h];
        #pragma unroll
        for (int j = 0; j < 16; j++) ad[j] += ps[j][i] * wv;
    }
    #pragma unroll
    for (int j = 0; j < 16; j++)
        y[(t0 + j) * H + h] = ad[j];
}

// ============================================================
// 3) routed experts: 1 block per expert, streams weights once.
// ============================================================
template <int NT>
__device__ __forceinline__ void expert_chunk(
    const float* __restrict__ x, const float* __restrict__ wg,
    const float* __restrict__ wu, const float* __restrict__ wd,
    float* __restrict__ y, const int* __restrict__ tokp,
    const float* __restrict__ wtp, int nt, float (*ps)[I_DIM], int tid)
{
    int   tk[NT];
    float wt[NT];
    #pragma unroll
    for (int j = 0; j < NT; j++) {
        int jj = (j < nt) ? j : (nt - 1);
        tk[j] = tokp[jj];
        wt[j] = (j < nt) ? wtp[j] : 0.f;
    }

    float a1[NT], a3[NT];
    #pragma unroll
    for (int j = 0; j < NT; j++) { a1[j] = 0.f; a3[j] = 0.f; }

    for (int h = 0; h < H; h++) {
        float g = wg[h * I_DIM + tid];
        float u = wu[h * I_DIM + tid];
        #pragma unroll
        for (int j = 0; j < NT; j++) {
            float xv = __ldg(x + (size_t)tk[j] * H + h);
            a1[j] += xv * g;
            a3[j] += xv * u;
        }
    }
    #pragma unroll
    for (int j = 0; j < NT; j++) {
        float v = a1[j];
        ps[j][tid] = (v / (1.f + expf(-v))) * a3[j];
    }
    __syncthreads();

    #pragma unroll
    for (int hb = 0; hb < 4; hb++) {
        int h = hb * 256 + tid;
        float ad[NT];
        #pragma unroll
        for (int j = 0; j < NT; j++) ad[j] = 0.f;
        for (int i = 0; i < I_DIM; i++) {
            float wv = wd[i * H + h];
            #pragma unroll
            for (int j = 0; j < NT; j++) ad[j] += ps[j][i] * wv;
        }
        #pragma unroll
        for (int j = 0; j < NT; j++)
            if (j < nt)
                atomicAdd(&y[(size_t)tk[j] * H + h], wt[j] * ad[j]);
    }
    __syncthreads();  // protect ps before next chunk
}

__global__ void k_expert(const float* __restrict__ x,
                         const float* __restrict__ w_gate,
                         const float* __restrict__ w_up,
                         const float* __restrict__ w_down,
                         float* __restrict__ y)
{
    __shared__ float ps[16][I_DIM];  // 16 KB
    int e = blockIdx.x;
    int n = d_cnt[e];
    if (n == 0) return;
    int tid = threadIdx.x;
    const float* wg = w_gate + (size_t)e * H * I_DIM;
    const float* wu = w_up   + (size_t)e * H * I_DIM;
    const float* wd = w_down + (size_t)e * I_DIM * H;

    for (int c = 0; c < n; c += 16) {
        int nt = min(16, n - c);
        const int*   tokp = d_tokbuf + e * T + c;
        const float* wtp  = d_wbuf   + e * T + c;
        if      (nt <= 4) expert_chunk<4>(x, wg, wu, wd, y, tokp, wtp, nt, ps, tid);
        else if (nt <= 8) expert_chunk<8>(x, wg, wu, wd, y, tokp, wtp, nt, ps, tid);
        else              expert_chunk<16>(x, wg, wu, wd, y, tokp, wtp, nt, ps, tid);
    }
}

// ============================================================
extern "C" void kernel_launch(void* const* d_in, const int* in_sizes, int n_in,
                              void* d_out, int out_size)
{
    const float* x   = (const float*)d_in[0];  // [1,1,T,H]
    const float* gw  = (const float*)d_in[1];  // [E,H]
    const float* eb  = (const float*)d_in[2];  // [E]
    const float* wg  = (const float*)d_in[3];  // [E,H,I]
    const float* wu  = (const float*)d_in[4];  // [E,H,I]
    const float* wd  = (const float*)d_in[5];  // [E,I,H]
    const float* swg = (const float*)d_in[6];  // [H,I]
    const float* swu = (const float*)d_in[7];  // [H,I]
    const float* swd = (const float*)d_in[8];  // [I,H]
    float* y = (float*)d_out;                  // [1,1,T,H] fp32

    k_zero<<<1, 256>>>();
    k_route<<<64, 256>>>(x, gw, eb);
    k_shared_a<<<64, 256>>>(x, swg, swu);
    k_shared_b<<<64, 256>>>(swd, y);
    k_expert<<<256, 256>>>(x, wg, wu, wd, y);
}

// round 2
// speedup vs baseline: 7.2909x; 7.2909x over previous
#include <cuda_runtime.h>
#include <math.h>

#define T 256
#define H 1024
#define E 256
#define I_DIM 256
#define SEG_CAP 16
#define NSEG_MAX 416
#define NSLOT (2048 + 256)

typedef unsigned long long u64;

// ---- static scratch ----
__device__ int   d_cnt[E];
__device__ int   d_off[E];
__device__ int   d_tokbuf[E * T];
__device__ float d_wbuf[E * T];
__device__ int   d_nseg;
__device__ int   d_seg_e[NSEG_MAX];
__device__ int   d_seg_nt[NSEG_MAX];
__device__ int   d_seg_slot0[NSEG_MAX];
__device__ int   d_seg_tok[NSEG_MAX * SEG_CAP];
__device__ float d_seg_wt[NSEG_MAX * SEG_CAP];
__device__ __align__(16) float d_ps[NSLOT * I_DIM];

// ---- f32x2 helpers ----
__device__ __forceinline__ u64 dup2(float v) {
    u64 r; asm("mov.b64 %0,{%1,%1};" : "=l"(r) : "f"(v)); return r;
}
__device__ __forceinline__ u64 fma2(u64 a, u64 b, u64 c) {
    u64 d; asm("fma.rn.f32x2 %0,%1,%2,%3;" : "=l"(d) : "l"(a), "l"(b), "l"(c)); return d;
}
__device__ __forceinline__ u64 add2(u64 a, u64 b) {
    u64 d; asm("add.rn.f32x2 %0,%1,%2;" : "=l"(d) : "l"(a), "l"(b)); return d;
}
__device__ __forceinline__ float2 unpk(u64 a) {
    float2 f; asm("mov.b64 {%0,%1},%2;" : "=f"(f.x), "=f"(f.y) : "l"(a)); return f;
}

// ============================================================
// 0) zero per-expert counters
// ============================================================
__global__ void k_zero() { d_cnt[threadIdx.x] = 0; }

// ============================================================
// 0b) zero output
// ============================================================
__global__ void k_yzero(float4* y) { y[blockIdx.x * 256 + threadIdx.x] = make_float4(0.f, 0.f, 0.f, 0.f); }

// ============================================================
// 1) gate logits + noaux_tc routing. 4 tokens per block, 256 thr.
// ============================================================
__global__ void k_route(const float* __restrict__ x,
                        const float* __restrict__ gw,
                        const float* __restrict__ ebias)
{
    __shared__ float xs[4][H];
    __shared__ float s_scores[4][E];
    __shared__ float s_sc[4][E];

    int tid  = threadIdx.x;
    int lane = tid & 31;
    int wid  = tid >> 5;
    int t0   = blockIdx.x * 4;

    for (int t = 0; t < 4; t++)
        for (int k = tid; k < H; k += 256)
            xs[t][k] = x[(t0 + t) * H + k];
    __syncthreads();

    for (int eo = 0; eo < 32; eo++) {
        int e = wid * 32 + eo;
        const float* wr = gw + e * H;
        float a0 = 0.f, a1 = 0.f, a2 = 0.f, a3 = 0.f;
        #pragma unroll 4
        for (int k = 0; k < 32; k++) {
            float wv = wr[k * 32 + lane];
            a0 += wv * xs[0][k * 32 + lane];
            a1 += wv * xs[1][k * 32 + lane];
            a2 += wv * xs[2][k * 32 + lane];
            a3 += wv * xs[3][k * 32 + lane];
        }
        for (int off = 16; off; off >>= 1) {
            a0 += __shfl_xor_sync(~0u, a0, off);
            a1 += __shfl_xor_sync(~0u, a1, off);
            a2 += __shfl_xor_sync(~0u, a2, off);
            a3 += __shfl_xor_sync(~0u, a3, off);
        }
        if (lane == 0) {
            float b = ebias[e];
            float s;
            s = 1.f / (1.f + expf(-a0)); s_scores[0][e] = s; s_sc[0][e] = s + b;
            s = 1.f / (1.f + expf(-a1)); s_scores[1][e] = s; s_sc[1][e] = s + b;
            s = 1.f / (1.f + expf(-a2)); s_scores[2][e] = s; s_sc[2][e] = s + b;
            s = 1.f / (1.f + expf(-a3)); s_scores[3][e] = s; s_sc[3][e] = s + b;
        }
    }
    __syncthreads();

    if (wid < 4) {
        int t     = wid;
        int tglob = t0 + t;

        float gs[8];
        #pragma unroll
        for (int g = 0; g < 8; g++) {
            float v  = s_sc[t][g * 32 + lane];
            float m1 = v; int i1 = lane;
            for (int off = 16; off; off >>= 1) {
                float ov = __shfl_xor_sync(~0u, m1, off);
                int   oi = __shfl_xor_sync(~0u, i1, off);
                if (ov > m1 || (ov == m1 && oi < i1)) { m1 = ov; i1 = oi; }
            }
            float v2 = (lane == i1) ? -INFINITY : v;
            for (int off = 16; off; off >>= 1)
                v2 = fmaxf(v2, __shfl_xor_sync(~0u, v2, off));
            gs[g] = m1 + v2;
        }

        unsigned gmask = 0;
        #pragma unroll
        for (int r = 0; r < 4; r++) {
            float bv = -INFINITY; int bg = 0;
            #pragma unroll
            for (int g = 0; g < 8; g++)
                if (!((gmask >> g) & 1) && gs[g] > bv) { bv = gs[g]; bg = g; }
            gmask |= 1u << bg;
        }

        float mv[8];
        #pragma unroll
        for (int j = 0; j < 8; j++)
            mv[j] = ((gmask >> j) & 1) ? s_sc[t][lane + 32 * j] : -INFINITY;

        int sel[8];
        #pragma unroll
        for (int r = 0; r < 8; r++) {
            float bv = -INFINITY; int be = 1 << 30;
            #pragma unroll
            for (int j = 0; j < 8; j++) {
                int e = lane + 32 * j;
                if (mv[j] > bv || (mv[j] == bv && e < be)) { bv = mv[j]; be = e; }
            }
            for (int off = 16; off; off >>= 1) {
                float ov = __shfl_xor_sync(~0u, bv, off);
                int   oe = __shfl_xor_sync(~0u, be, off);
                if (ov > bv || (ov == bv && oe < be)) { bv = ov; be = oe; }
            }
            sel[r] = be;
            if ((be & 31) == lane) mv[be >> 5] = -INFINITY;
        }

        float myv = (lane < 8) ? s_scores[t][sel[lane]] : 0.f;
        float sum = myv;
        for (int off = 16; off; off >>= 1)
            sum += __shfl_xor_sync(~0u, sum, off);
        if (lane < 8) {
            float wt = myv / (sum + 1e-20f) * 2.5f;
            int e = sel[lane];
            int pos = atomicAdd(&d_cnt[e], 1);
            d_tokbuf[e * T + pos] = tglob;
            d_wbuf[e * T + pos]  = wt;
        }
    }
}

// ============================================================
// 2) scan: per-expert offsets + segment list (+16 shared segs)
// ============================================================
__global__ void k_scan()
{
    __shared__ int s1[E], s2[E];
    int e = threadIdx.x;
    int n = d_cnt[e];

    s1[e] = n; __syncthreads();
    for (int d = 1; d < E; d <<= 1) {
        int v = (e >= d) ? s1[e - d] : 0;
        __syncthreads();
        s1[e] += v;
        __syncthreads();
    }
    int off = s1[e] - n;
    d_off[e] = off;

    int nseg = (n + SEG_CAP - 1) / SEG_CAP;
    s2[e] = nseg; __syncthreads();
    for (int d = 1; d < E; d <<= 1) {
        int v = (e >= d) ? s2[e - d] : 0;
        __syncthreads();
        s2[e] += v;
        __syncthreads();
    }
    int segbase = 16 + (s2[e] - nseg);
    if (e == E - 1) d_nseg = 16 + s2[E - 1];

    for (int si = 0; si < nseg; si++) {
        int sidx = segbase + si;
        int st   = si * SEG_CAP;
        int cnt  = min(SEG_CAP, n - st);
        d_seg_e[sidx]     = e;
        d_seg_nt[sidx]    = cnt;
        d_seg_slot0[sidx] = off + st;
        for (int j = 0; j < cnt; j++) {
            d_seg_tok[sidx * SEG_CAP + j] = d_tokbuf[e * T + st + j];
            d_seg_wt[sidx * SEG_CAP + j]  = d_wbuf[e * T + st + j];
        }
    }

    // shared-expert segments at [0..16)
    if (e < 16) {
        d_seg_e[e]     = E;          // marker: shared
        d_seg_nt[e]    = SEG_CAP;
        d_seg_slot0[e] = 2048 + e * SEG_CAP;
        for (int j = 0; j < SEG_CAP; j++) {
            d_seg_tok[e * SEG_CAP + j] = e * SEG_CAP + j;
            d_seg_wt[e * SEG_CAP + j]  = 1.0f;
        }
    }
}

// ============================================================
// 3) up/gate: per segment, stream wg+wu once, f32x2 columns
// ============================================================
template <int NT>
__device__ __forceinline__ void up_body(
    const float* __restrict__ x,
    const u64* __restrict__ wg2, const u64* __restrict__ wu2,
    float* __restrict__ psout, int nt, const int* __restrict__ segtok,
    int ic, float* xs, int* s_tok, int tid)
{
    int c2 = tid & 63;      // column-pair within 128-col chunk
    int hg = tid >> 6;      // one of 4 h-groups

    if (tid < SEG_CAP) s_tok[tid] = segtok[min(tid, nt - 1)];

    u64 a1[NT], a3[NT];
    #pragma unroll
    for (int j = 0; j < NT; j++) { a1[j] = 0ull; a3[j] = 0ull; }

    for (int c = 0; c < 2; c++) {
        __syncthreads();
        {   // stage x tile [NT][512] (float4 coalesced)
            float4* xs4 = (float4*)xs;
            for (int u = tid; u < NT * 128; u += 256) {
                int j = u >> 7, hh = u & 127;
                xs4[u] = *(const float4*)(x + (size_t)s_tok[j] * H + c * 512 + hh * 4);
            }
        }
        __syncthreads();

        int hbase = c * 512 + hg * 128;
        const u64* wgp = wg2 + (size_t)hbase * 128 + ic * 64 + c2;
        const u64* wup = wu2 + (size_t)hbase * 128 + ic * 64 + c2;
        const float* xr = xs + hg * 128;
        #pragma unroll 4
        for (int k = 0; k < 128; k++) {
            u64 g = wgp[(size_t)k * 128];
            u64 u = wup[(size_t)k * 128];
            #pragma unroll
            for (int j = 0; j < NT; j++) {
                u64 xx = dup2(xr[j * 512 + k]);
                a1[j] = fma2(xx, g, a1[j]);
                a3[j] = fma2(xx, u, a3[j]);
            }
        }
    }

    // reduce across 4 h-groups (overlay red buffer on xs)
    u64* red = (u64*)xs;   // 4 tokens * 2 arrays * 4 groups * 64 pairs = 2048 u64
    for (int tg = 0; tg < NT; tg += 4) {
        __syncthreads();
        #pragma unroll
        for (int jj = 0; jj < 4; jj++) {
            int j = tg + jj;
            if (j < NT) {
                red[((jj * 2 + 0) * 4 + hg) * 64 + c2] = a1[j];
                red[((jj * 2 + 1) * 4 + hg) * 64 + c2] = a3[j];
            }
        }
        __syncthreads();
        int jj = tid >> 6, c2r = tid & 63;
        int j = tg + jj;
        if (j < NT && j < nt) {
            u64 sA = add2(add2(red[((jj * 2 + 0) * 4 + 0) * 64 + c2r],
                               red[((jj * 2 + 0) * 4 + 1) * 64 + c2r]),
                          add2(red[((jj * 2 + 0) * 4 + 2) * 64 + c2r],
                               red[((jj * 2 + 0) * 4 + 3) * 64 + c2r]));
            u64 sB = add2(add2(red[((jj * 2 + 1) * 4 + 0) * 64 + c2r],
                               red[((jj * 2 + 1) * 4 + 1) * 64 + c2r]),
                          add2(red[((jj * 2 + 1) * 4 + 2) * 64 + c2r],
                               red[((jj * 2 + 1) * 4 + 3) * 64 + c2r]));
            float2 v = unpk(sA), m = unpk(sB);
            float r0 = v.x / (1.f + expf(-v.x)) * m.x;
            float r1 = v.y / (1.f + expf(-v.y)) * m.y;
            *(float2*)(psout + j * I_DIM + ic * 128 + c2r * 2) = make_float2(r0, r1);
        }
    }
}

__global__ void __launch_bounds__(256, 2) k_up(
    const float* __restrict__ x,
    const float* __restrict__ w_gate, const float* __restrict__ w_up,
    const float* __restrict__ sw_gate, const float* __restrict__ sw_up)
{
    __shared__ float xs[16 * 512];   // 32 KB, doubles as reduction buffer
    __shared__ int   s_tok[SEG_CAP];
    int seg = blockIdx.y;
    if (seg >= d_nseg) return;
    int e     = d_seg_e[seg];
    int nt    = d_seg_nt[seg];
    int slot0 = d_seg_slot0[seg];
    int ic    = blockIdx.x;
    const float *wg, *wu;
    if (e < E) { wg = w_gate + (size_t)e * H * I_DIM; wu = w_up + (size_t)e * H * I_DIM; }
    else       { wg = sw_gate; wu = sw_up; }
    const int* segtok = d_seg_tok + seg * SEG_CAP;
    float* psout = d_ps + (size_t)slot0 * I_DIM;
    int tid = threadIdx.x;

    if      (nt <= 4)  up_body<4>(x, (const u64*)wg, (const u64*)wu, psout, nt, segtok, ic, xs, s_tok, tid);
    else if (nt <= 8)  up_body<8>(x, (const u64*)wg, (const u64*)wu, psout, nt, segtok, ic, xs, s_tok, tid);
    else if (nt <= 12) up_body<12>(x, (const u64*)wg, (const u64*)wu, psout, nt, segtok, ic, xs, s_tok, tid);
    else               up_body<16>(x, (const u64*)wg, (const u64*)wu, psout, nt, segtok, ic, xs, s_tok, tid);
}

// ============================================================
// 4) down projection: stream wd once, f32x2 h-pairs, REDG into y
// ============================================================
template <int NT>
__device__ __forceinline__ void down_body(
    const u64* __restrict__ wd2, const float* __restrict__ psin,
    float* __restrict__ y, int nt,
    const int* __restrict__ segtok, const float* __restrict__ segwt,
    int hc, float* ps_s, int* s_tok, float* s_wt, int tid)
{
    if (tid < SEG_CAP) {
        s_tok[tid] = segtok[min(tid, nt - 1)];
        s_wt[tid]  = (tid < nt) ? segwt[tid] : 0.f;
    }
    {   // stage ps [NT][256] via float4
        float4* p4 = (float4*)ps_s;
        for (int u = tid; u < NT * 64; u += 256) {
            int j = u >> 6, i4 = u & 63;
            p4[u] = (j < nt) ? ((const float4*)psin)[j * 64 + i4]
                             : make_float4(0.f, 0.f, 0.f, 0.f);
        }
    }
    __syncthreads();

    u64 acc[NT];
    #pragma unroll
    for (int j = 0; j < NT; j++) acc[j] = 0ull;

    const u64* wp = wd2 + hc * 256 + tid;
    #pragma unroll 4
    for (int i = 0; i < I_DIM; i++) {
        u64 w = wp[(size_t)i * 512];
        #pragma unroll
        for (int j = 0; j < NT; j++)
            acc[j] = fma2(dup2(ps_s[j * I_DIM + i]), w, acc[j]);
    }

    int h0 = hc * 512 + tid * 2;
    #pragma unroll
    for (int j = 0; j < NT; j++) {
        if (j < nt) {
            float2 v = unpk(acc[j]);
            float w  = s_wt[j];
            atomicAdd(&y[(size_t)s_tok[j] * H + h0],     w * v.x);
            atomicAdd(&y[(size_t)s_tok[j] * H + h0 + 1], w * v.y);
        }
    }
}

__global__ void __launch_bounds__(256, 3) k_down(
    const float* __restrict__ w_down, const float* __restrict__ sw_down,
    float* __restrict__ y)
{
    __shared__ float ps_s[16 * I_DIM];   // 16 KB
    __shared__ int   s_tok[SEG_CAP];
    __shared__ float s_wt[SEG_CAP];
    int seg = blockIdx.y;
    if (seg >= d_nseg) return;
    int e     = d_seg_e[seg];
    int nt    = d_seg_nt[seg];
    int slot0 = d_seg_slot0[seg];
    int hc    = blockIdx.x;
    const float* wd = (e < E) ? (w_down + (size_t)e * I_DIM * H) : sw_down;
    const int*   segtok = d_seg_tok + seg * SEG_CAP;
    const float* segwt  = d_seg_wt + seg * SEG_CAP;
    const float* psin   = d_ps + (size_t)slot0 * I_DIM;
    int tid = threadIdx.x;

    if      (nt <= 4)  down_body<4>((const u64*)wd, psin, y, nt, segtok, segwt, hc, ps_s, s_tok, s_wt, tid);
    else if (nt <= 8)  down_body<8>((const u64*)wd, psin, y, nt, segtok, segwt, hc, ps_s, s_tok, s_wt, tid);
    else if (nt <= 12) down_body<12>((const u64*)wd, psin, y, nt, segtok, segwt, hc, ps_s, s_tok, s_wt, tid);
    else               down_body<16>((const u64*)wd, psin, y, nt, segtok, segwt, hc, ps_s, s_tok, s_wt, tid);
}

// ============================================================
extern "C" void kernel_launch(void* const* d_in, const int* in_sizes, int n_in,
                              void* d_out, int out_size)
{
    const float* x   = (const float*)d_in[0];
    const float* gw  = (const float*)d_in[1];
    const float* eb  = (const float*)d_in[2];
    const float* wg  = (const float*)d_in[3];
    const float* wu  = (const float*)d_in[4];
    const float* wd  = (const float*)d_in[5];
    const float* swg = (const float*)d_in[6];
    const float* swu = (const float*)d_in[7];
    const float* swd = (const float*)d_in[8];
    float* y = (float*)d_out;

    k_zero<<<1, 256>>>();
    k_route<<<64, 256>>>(x, gw, eb);
    k_scan<<<1, 256>>>();
    k_yzero<<<256, 256>>>((float4*)y);
    k_up<<<dim3(2, NSEG_MAX), 256>>>(x, wg, wu, swg, swu);
    k_down<<<dim3(2, NSEG_MAX), 256>>>(wd, swd, y);
}